// round 3
// baseline (speedup 1.0000x reference)
#include <cuda_runtime.h>
#include <math.h>

// Problem constants
#define BB 4
#define NN 2048
#define DD 1024
#define EE 16
#define CC 256
#define BE (BB*EE)            // 64 (b,e) pairs
#define DISP_ELEMS (BB*NN*EE*CC)   // 33554432

#define FLT_MIN_NORMAL 1.17549435e-38f

// Scratch (no allocations allowed -> __device__ globals)
__device__ float g_logits[BE * NN];   // affinity logits (already /exp(temp))
__device__ int   g_rank[BE * NN];     // rank of token n for (b,e), -1 if not selected
__device__ float g_aff[BE * NN];      // softmax affinity of token n for (b,e)

// ---------------------------------------------------------------------------
// K1: gate logits.  One warp computes 4 tokens x 16 experts.
// key: [B,N,D] f32, query: [E,D] f32, temp: scalar (log-temperature)
// ---------------------------------------------------------------------------
__global__ void __launch_bounds__(128)
logits_kernel(const float* __restrict__ key,
              const float* __restrict__ query,
              const float* __restrict__ temp)
{
    const int lane = threadIdx.x & 31;
    const int warp = threadIdx.x >> 5;
    const int t0   = (blockIdx.x * 4 + warp) * 4;   // first of 4 flat tokens in [0, B*N)

    float acc[4][16];
#pragma unroll
    for (int t = 0; t < 4; ++t)
#pragma unroll
        for (int e = 0; e < 16; ++e) acc[t][e] = 0.0f;

    // d-sweep: each lane owns a float4 chunk, 8 sweeps cover D=1024
#pragma unroll
    for (int d0 = 0; d0 < DD; d0 += 128) {
        const int d = d0 + lane * 4;
        float4 kv[4];
#pragma unroll
        for (int t = 0; t < 4; ++t)
            kv[t] = *reinterpret_cast<const float4*>(key + (size_t)(t0 + t) * DD + d);
#pragma unroll
        for (int e = 0; e < 16; ++e) {
            float4 qv = *reinterpret_cast<const float4*>(query + e * DD + d);
#pragma unroll
            for (int t = 0; t < 4; ++t) {
                acc[t][e] += kv[t].x * qv.x;
                acc[t][e] += kv[t].y * qv.y;
                acc[t][e] += kv[t].z * qv.z;
                acc[t][e] += kv[t].w * qv.w;
            }
        }
    }

    const float et = expf(temp[0]);   // exp(log-temp); divide logits by it

#pragma unroll
    for (int t = 0; t < 4; ++t) {
#pragma unroll
        for (int e = 0; e < 16; ++e) {
            float s = acc[t][e];
            s += __shfl_xor_sync(0xffffffffu, s, 16);
            s += __shfl_xor_sync(0xffffffffu, s, 8);
            s += __shfl_xor_sync(0xffffffffu, s, 4);
            s += __shfl_xor_sync(0xffffffffu, s, 2);
            s += __shfl_xor_sync(0xffffffffu, s, 1);
            if (lane == e) {
                const int tok = t0 + t;
                const int b = tok >> 11;        // / NN
                const int n = tok & (NN - 1);
                g_logits[(b * EE + e) * NN + n] = s / et;
            }
        }
    }
}

// ---------------------------------------------------------------------------
// K2: softmax over tokens + stable top-256 per (b,e) via full bitonic sort.
// Affinity is FLUSHED TO ZERO below FLT_MIN (normal) to match the reference's
// FTZ zero-set (this defines the tie region, which dominates the selection).
// Sort key (descending): hi32 = affinity fp32 bits (aff >= 0 -> monotone),
// lo32 = (2047 - n) so ties break toward the LOWER token index (jax top_k).
// ---------------------------------------------------------------------------
__global__ void __launch_bounds__(256)
topk_kernel()
{
    __shared__ float aff[NN];
    __shared__ unsigned long long keys[NN];
    __shared__ float red[256];

    const int tid = threadIdx.x;
    const int be  = blockIdx.x;
    const float* g = g_logits + (size_t)be * NN;

    // local values + max
    float v[8];
    float m = -INFINITY;
#pragma unroll
    for (int k = 0; k < 8; ++k) {
        v[k] = g[tid + k * 256];
        m = fmaxf(m, v[k]);
    }
    red[tid] = m;
    __syncthreads();
    for (int s = 128; s > 0; s >>= 1) {
        if (tid < s) red[tid] = fmaxf(red[tid], red[tid + s]);
        __syncthreads();
    }
    m = red[0];
    __syncthreads();

    // exp + sum
    float u[8];
    float loc = 0.0f;
#pragma unroll
    for (int k = 0; k < 8; ++k) {
        u[k] = expf(v[k] - m);
        loc += u[k];
    }
    red[tid] = loc;
    __syncthreads();
    for (int s = 128; s > 0; s >>= 1) {
        if (tid < s) red[tid] = red[tid] + red[tid + s];
        __syncthreads();
    }
    const float ssum = red[0];
    __syncthreads();

    // affinity (with subnormal flush) + sort keys
#pragma unroll
    for (int k = 0; k < 8; ++k) {
        const int n = tid + k * 256;
        float a = u[k] / ssum;                   // IEEE div (no fast-math)
        if (a < FLT_MIN_NORMAL) a = 0.0f;        // match reference FTZ zero-set
        aff[n] = a;
        keys[n] = ((unsigned long long)__float_as_uint(a) << 32)
                | (unsigned)(NN - 1 - n);
    }
    __syncthreads();

    // bitonic sort, final order descending
    for (int kk = 2; kk <= NN; kk <<= 1) {
        for (int j = kk >> 1; j > 0; j >>= 1) {
            for (int i = tid; i < NN; i += 256) {
                const int l = i ^ j;
                if (l > i) {
                    const unsigned long long a = keys[i];
                    const unsigned long long b = keys[l];
                    const bool desc = ((i & kk) == 0);
                    if (desc ? (a < b) : (a > b)) {
                        keys[i] = b;
                        keys[l] = a;
                    }
                }
            }
            __syncthreads();
        }
    }

    // emit per-token affinity + inverse rank map
#pragma unroll
    for (int k = 0; k < 8; ++k) {
        const int n = tid + k * 256;
        g_aff[(size_t)be * NN + n]  = aff[n];
        g_rank[(size_t)be * NN + n] = -1;
    }
    __syncthreads();   // order -1 init before the scatter below (intra-block)

    // tid == rank slot c (blockDim == 256 == capacity)
    {
        const int tok = (NN - 1) - (int)(unsigned)(keys[tid] & 0xffffffffu);
        g_rank[(size_t)be * NN + tok] = tid;
    }
}

// ---------------------------------------------------------------------------
// K3: single-pass output fill. One block per (b,n). Writes dispatch AND
// combine tiles (E*C = 4096 floats each) as float4 streams; zeros everywhere
// except the one hit slot per selected (b,e). Also writes the 2 trailing zeros.
// ---------------------------------------------------------------------------
__global__ void __launch_bounds__(256)
fill_kernel(float* __restrict__ out)
{
    const int bn = blockIdx.x;          // [0, B*N)
    const int b  = bn >> 11;
    const int n  = bn & (NN - 1);

    __shared__ int   s_r[EE];
    __shared__ float s_a[EE];
    if (threadIdx.x < EE) {
        const int idx = (b * EE + threadIdx.x) * NN + n;
        s_r[threadIdx.x] = g_rank[idx];
        s_a[threadIdx.x] = g_aff[idx];
    }
    __syncthreads();

    float4* dsp = reinterpret_cast<float4*>(out) + (size_t)bn * (EE * CC / 4);
    float4* cmb = dsp + (size_t)(DISP_ELEMS / 4);

#pragma unroll
    for (int kk = 0; kk < 4; ++kk) {
        const int i  = threadIdx.x + kk * 256;   // [0, 1024) float4 within (e,c)
        const int e  = i >> 6;                   // 64 float4 per expert (C/4)
        const int c4 = i & 63;
        const int r  = s_r[e];                   // -1 or rank in [0,256)

        float4 z  = make_float4(0.f, 0.f, 0.f, 0.f);
        float4 zc = z;
        if ((r >> 2) == c4) {                    // r == -1 -> -1 != c4, never hits
            const int lr = r & 3;
            const float a = s_a[e];
            if      (lr == 0) { z.x = 1.f; zc.x = a; }
            else if (lr == 1) { z.y = 1.f; zc.y = a; }
            else if (lr == 2) { z.z = 1.f; zc.z = a; }
            else              { z.w = 1.f; zc.w = a; }
        }
        dsp[i] = z;
        cmb[i] = zc;
    }

    if (bn == 0 && threadIdx.x == 0) {
        out[2 * DISP_ELEMS]     = 0.f;   // zero #1
        out[2 * DISP_ELEMS + 1] = 0.f;   // zero #2
    }
}

// ---------------------------------------------------------------------------
extern "C" void kernel_launch(void* const* d_in, const int* in_sizes, int n_in,
                              void* d_out, int out_size)
{
    const float* key   = (const float*)d_in[0];   // [B,N,D]
    const float* query = (const float*)d_in[1];   // [E,D]
    const float* temp  = (const float*)d_in[2];   // scalar log-temp

    (void)in_sizes; (void)n_in; (void)out_size;

    logits_kernel<<<(BB * NN) / 16, 128>>>(key, query, temp); // 512 blocks, warp=4 tokens
    topk_kernel<<<BE, 256>>>();                                // 64 blocks
    fill_kernel<<<BB * NN, 256>>>((float*)d_out);              // 8192 blocks
}

// round 4
// speedup vs baseline: 1.3987x; 1.3987x over previous
#include <cuda_runtime.h>
#include <math.h>

// Problem constants
#define BB 4
#define NN 2048
#define DD 1024
#define EE 16
#define CC 256
#define BE (BB*EE)                 // 64 (b,e) pairs
#define DISP_ELEMS (BB*NN*EE*CC)   // 33554432 floats per output tensor

#define FLT_MIN_NORMAL 1.17549435e-38f

#define LOGITS_BLOCKS 1024         // 128 thr, 4 warps x 2 tokens = 8 tokens/block
#define ZFILL_BLOCKS  2048
#define OUT_F4 (2 * DISP_ELEMS / 4)   // 16777216 float4 covering both tensors

// Scratch (no allocations allowed -> __device__ global)
__device__ float g_logits[BE * NN];   // affinity logits (already /exp(temp)), layout [(b*EE+e)*NN + n]

// ---------------------------------------------------------------------------
// KA: fused gate-logits + output zero-fill.
//   Blocks [0, LOGITS_BLOCKS): one warp computes 2 tokens x 16 experts.
//   Blocks [LOGITS_BLOCKS, +ZFILL_BLOCKS): stream zeros over the whole output.
// The zero-fill is data-independent, so it overlaps the logits compute in one
// launch; the hit slots are scattered later by K2 (stream-ordered after KA).
// ---------------------------------------------------------------------------
__global__ void __launch_bounds__(128)
fused_logits_zfill_kernel(const float* __restrict__ key,
                          const float* __restrict__ query,
                          const float* __restrict__ temp,
                          float* __restrict__ out)
{
    const int tid = threadIdx.x;

    if (blockIdx.x >= LOGITS_BLOCKS) {
        // ---- zero-fill branch: grid-stride float4 stores over 268 MB ----
        const int zb = blockIdx.x - LOGITS_BLOCKS;
        float4* o4 = reinterpret_cast<float4*>(out);
        const float4 z = make_float4(0.f, 0.f, 0.f, 0.f);
        size_t i = (size_t)zb * 128 + tid;
        const size_t stride = (size_t)ZFILL_BLOCKS * 128;
#pragma unroll 4
        for (; i < OUT_F4; i += stride)
            o4[i] = z;
        if (zb == 0 && tid == 0) {
            out[2 * DISP_ELEMS]     = 0.f;   // trailing zero #1
            out[2 * DISP_ELEMS + 1] = 0.f;   // trailing zero #2
        }
        return;
    }

    // ---- logits branch ----
    const int lane = tid & 31;
    const int warp = tid >> 5;
    const int t0   = blockIdx.x * 8 + warp * 2;   // first of 2 flat tokens in [0, B*N)

    float acc[2][16];
#pragma unroll
    for (int t = 0; t < 2; ++t)
#pragma unroll
        for (int e = 0; e < 16; ++e) acc[t][e] = 0.0f;

#pragma unroll
    for (int d0 = 0; d0 < DD; d0 += 128) {
        const int d = d0 + lane * 4;
        float4 kv0 = *reinterpret_cast<const float4*>(key + (size_t)t0 * DD + d);
        float4 kv1 = *reinterpret_cast<const float4*>(key + (size_t)(t0 + 1) * DD + d);
#pragma unroll
        for (int e = 0; e < 16; ++e) {
            float4 qv = *reinterpret_cast<const float4*>(query + e * DD + d);
            acc[0][e] += kv0.x * qv.x;  acc[0][e] += kv0.y * qv.y;
            acc[0][e] += kv0.z * qv.z;  acc[0][e] += kv0.w * qv.w;
            acc[1][e] += kv1.x * qv.x;  acc[1][e] += kv1.y * qv.y;
            acc[1][e] += kv1.z * qv.z;  acc[1][e] += kv1.w * qv.w;
        }
    }

    const float et = expf(temp[0]);   // exp(log-temp); divide logits by it

#pragma unroll
    for (int t = 0; t < 2; ++t) {
#pragma unroll
        for (int e = 0; e < 16; ++e) {
            float s = acc[t][e];
            s += __shfl_xor_sync(0xffffffffu, s, 16);
            s += __shfl_xor_sync(0xffffffffu, s, 8);
            s += __shfl_xor_sync(0xffffffffu, s, 4);
            s += __shfl_xor_sync(0xffffffffu, s, 2);
            s += __shfl_xor_sync(0xffffffffu, s, 1);
            if (lane == e) {
                const int tok = t0 + t;
                const int b = tok >> 11;        // / NN
                const int n = tok & (NN - 1);
                g_logits[(b * EE + e) * NN + n] = s / et;
            }
        }
    }
}

// ---------------------------------------------------------------------------
// K2: softmax over tokens + stable top-256 per (b,e) via full bitonic sort,
// then direct scatter of the hit slots into the (already zeroed) output.
// 1024 threads: each thread owns exactly one compare-exchange per pass.
// Affinity is FLUSHED TO ZERO below FLT_MIN (normal) to match the reference's
// FTZ zero-set (defines the tie region, which dominates selection).
// Sort key (descending): hi32 = affinity fp32 bits (aff >= 0 -> monotone),
// lo32 = (2047 - n) so ties break toward the LOWER token index (jax top_k).
// ---------------------------------------------------------------------------
__global__ void __launch_bounds__(1024)
topk_scatter_kernel(float* __restrict__ out)
{
    __shared__ float aff[NN];
    __shared__ unsigned long long keys[NN];
    __shared__ float red[32];

    const int tid  = threadIdx.x;
    const int lane = tid & 31;
    const int wid  = tid >> 5;
    const int be   = blockIdx.x;
    const int b    = be >> 4;          // / EE
    const int e    = be & (EE - 1);
    const float* g = g_logits + (size_t)be * NN;

    // local values + block max
    const float v0 = g[tid];
    const float v1 = g[tid + 1024];
    float m = fmaxf(v0, v1);
#pragma unroll
    for (int s = 16; s > 0; s >>= 1) m = fmaxf(m, __shfl_xor_sync(0xffffffffu, m, s));
    if (lane == 0) red[wid] = m;
    __syncthreads();
    if (wid == 0) {
        float t = red[lane];
#pragma unroll
        for (int s = 16; s > 0; s >>= 1) t = fmaxf(t, __shfl_xor_sync(0xffffffffu, t, s));
        if (lane == 0) red[0] = t;
    }
    __syncthreads();
    m = red[0];
    __syncthreads();

    // exp + block sum
    const float u0 = expf(v0 - m);
    const float u1 = expf(v1 - m);
    float loc = u0 + u1;
#pragma unroll
    for (int s = 16; s > 0; s >>= 1) loc += __shfl_xor_sync(0xffffffffu, loc, s);
    if (lane == 0) red[wid] = loc;
    __syncthreads();
    if (wid == 0) {
        float t = red[lane];
#pragma unroll
        for (int s = 16; s > 0; s >>= 1) t += __shfl_xor_sync(0xffffffffu, t, s);
        if (lane == 0) red[0] = t;
    }
    __syncthreads();
    const float ssum = red[0];

    // affinity (with subnormal flush) + sort keys
    {
        float a0 = u0 / ssum;                       // IEEE div (no fast-math)
        float a1 = u1 / ssum;
        if (a0 < FLT_MIN_NORMAL) a0 = 0.0f;         // match reference FTZ zero-set
        if (a1 < FLT_MIN_NORMAL) a1 = 0.0f;
        aff[tid]        = a0;
        aff[tid + 1024] = a1;
        keys[tid] = ((unsigned long long)__float_as_uint(a0) << 32)
                  | (unsigned)(NN - 1 - tid);
        keys[tid + 1024] = ((unsigned long long)__float_as_uint(a1) << 32)
                  | (unsigned)(NN - 1 - (tid + 1024));
    }
    __syncthreads();

    // bitonic sort, final order descending; one compare-exchange per thread/pass
    for (int kk = 2; kk <= NN; kk <<= 1) {
        for (int j = kk >> 1; j > 0; j >>= 1) {
            const int i = ((tid & ~(j - 1)) << 1) | (tid & (j - 1));
            const int l = i | j;
            const unsigned long long a = keys[i];
            const unsigned long long bkey = keys[l];
            const bool desc = ((i & kk) == 0);
            if (desc ? (a < bkey) : (a > bkey)) {
                keys[i] = bkey;
                keys[l] = a;
            }
            __syncthreads();
        }
    }

    // scatter: rank slot c = tid (< capacity).  Output already zero-filled.
    if (tid < CC) {
        const int tok = (NN - 1) - (int)(unsigned)(keys[tid] & 0xffffffffu);
        const size_t addr = (((size_t)(b * NN + tok) * EE) + e) * CC + tid;
        out[addr]              = 1.0f;       // dispatch
        out[DISP_ELEMS + addr] = aff[tok];   // combine
    }
}

// ---------------------------------------------------------------------------
extern "C" void kernel_launch(void* const* d_in, const int* in_sizes, int n_in,
                              void* d_out, int out_size)
{
    const float* key   = (const float*)d_in[0];   // [B,N,D]
    const float* query = (const float*)d_in[1];   // [E,D]
    const float* temp  = (const float*)d_in[2];   // scalar log-temp

    (void)in_sizes; (void)n_in; (void)out_size;

    fused_logits_zfill_kernel<<<LOGITS_BLOCKS + ZFILL_BLOCKS, 128>>>(
        key, query, temp, (float*)d_out);
    topk_scatter_kernel<<<BE, 1024>>>((float*)d_out);
}

// round 8
// speedup vs baseline: 1.6383x; 1.1713x over previous
#include <cuda_runtime.h>
#include <math.h>

// Problem constants
#define BB 4
#define NN 2048
#define DD 1024
#define EE 16
#define CC 256
#define BE (BB*EE)                 // 64 (b,e) pairs
#define DISP_ELEMS (BB*NN*EE*CC)   // 33554432 floats per output tensor

#define FLT_MIN_NORMAL 1.17549435e-38f

#define LOGITS_BLOCKS 1024         // every 4th block; 4 warps x 2 tokens = 8 tokens/block
#define ZFILL_BLOCKS  3072
#define TOTAL_BLOCKS  4096
#define OUT_F4 (2 * DISP_ELEMS / 4)   // 16777216 float4 covering both tensors

typedef unsigned long long u64;

// Scratch (no allocations allowed -> __device__ global)
__device__ float g_logits[BE * NN];   // affinity logits (already /exp(temp)), [(b*EE+e)*NN + n]

// ---------------------------------------------------------------------------
// KA: fused gate-logits + output zero-fill, role-interleaved so every wave
// carries both DRAM store traffic (zfill) and FMA work (logits).
//   blockIdx % 4 == 3  -> logits block   (1024 total)
//   else               -> zero-fill block (3072 total)
// ---------------------------------------------------------------------------
__global__ void __launch_bounds__(128)
fused_logits_zfill_kernel(const float* __restrict__ key,
                          const float* __restrict__ query,
                          const float* __restrict__ temp,
                          float* __restrict__ out)
{
    const int tid = threadIdx.x;

    if ((blockIdx.x & 3) != 3) {
        // ---- zero-fill branch: grid-stride streaming float4 stores, 268 MB ----
        const int zb = blockIdx.x - ((blockIdx.x + 1) >> 2);   // dense zfill id [0,3072)
        float4* o4 = reinterpret_cast<float4*>(out);
        const float4 z = make_float4(0.f, 0.f, 0.f, 0.f);
        size_t i = (size_t)zb * 128 + tid;
        const size_t stride = (size_t)ZFILL_BLOCKS * 128;
#pragma unroll 4
        for (; i < OUT_F4; i += stride)
            __stcs(o4 + i, z);
        if (zb == 0 && tid == 0) {
            out[2 * DISP_ELEMS]     = 0.f;   // trailing zero #1
            out[2 * DISP_ELEMS + 1] = 0.f;   // trailing zero #2
        }
        return;
    }

    // ---- logits branch: one warp computes 2 tokens x 16 experts ----
    const int lid  = blockIdx.x >> 2;             // dense logits id [0,1024)
    const int lane = tid & 31;
    const int warp = tid >> 5;
    const int t0   = lid * 8 + warp * 2;          // first of 2 flat tokens in [0, B*N)

    float acc[2][16];
#pragma unroll
    for (int t = 0; t < 2; ++t)
#pragma unroll
        for (int e = 0; e < 16; ++e) acc[t][e] = 0.0f;

#pragma unroll
    for (int d0 = 0; d0 < DD; d0 += 128) {
        const int d = d0 + lane * 4;
        float4 kv0 = *reinterpret_cast<const float4*>(key + (size_t)t0 * DD + d);
        float4 kv1 = *reinterpret_cast<const float4*>(key + (size_t)(t0 + 1) * DD + d);
#pragma unroll
        for (int e = 0; e < 16; ++e) {
            float4 qv = *reinterpret_cast<const float4*>(query + e * DD + d);
            acc[0][e] += kv0.x * qv.x;  acc[0][e] += kv0.y * qv.y;
            acc[0][e] += kv0.z * qv.z;  acc[0][e] += kv0.w * qv.w;
            acc[1][e] += kv1.x * qv.x;  acc[1][e] += kv1.y * qv.y;
            acc[1][e] += kv1.z * qv.z;  acc[1][e] += kv1.w * qv.w;
        }
    }

    const float et = expf(temp[0]);   // exp(log-temp); divide logits by it

#pragma unroll
    for (int t = 0; t < 2; ++t) {
#pragma unroll
        for (int e = 0; e < 16; ++e) {
            float s = acc[t][e];
            s += __shfl_xor_sync(0xffffffffu, s, 16);
            s += __shfl_xor_sync(0xffffffffu, s, 8);
            s += __shfl_xor_sync(0xffffffffu, s, 4);
            s += __shfl_xor_sync(0xffffffffu, s, 2);
            s += __shfl_xor_sync(0xffffffffu, s, 1);
            if (lane == e) {
                const int tok = t0 + t;
                const int b = tok >> 11;        // / NN
                const int n = tok & (NN - 1);
                g_logits[(b * EE + e) * NN + n] = s / et;
            }
        }
    }
}

// ---------------------------------------------------------------------------
// K2: softmax + stable top-256 per (b,e) via register-resident bitonic sort,
// then direct scatter over the (already zeroed) output.
// Thread t owns elements {2t, 2t+1} in registers.
//   j == 1       : in-thread compare-exchange
//   j in [2,32]  : __shfl_xor with partner thread t^(j/2)   (no barriers)
//   j >= 64      : smem exchange, double-buffered, ONE __syncthreads per pass
// Only 15 of 66 passes hit a barrier (was 66).
// Affinity FLUSHED TO ZERO below FLT_MIN (normal) to match the reference's
// FTZ zero-set. Sort key (descending): hi32 = affinity fp32 bits,
// lo32 = (2047 - n) so ties break toward the LOWER token index (jax top_k).
// ---------------------------------------------------------------------------
__global__ void __launch_bounds__(1024)
topk_scatter_kernel(float* __restrict__ out)
{
    __shared__ float aff[NN];          // 8 KB
    __shared__ u64   xbuf[2][NN];      // 32 KB, double-buffered exchange
    __shared__ float red[32];

    const int tid  = threadIdx.x;
    const int lane = tid & 31;
    const int wid  = tid >> 5;
    const int be   = blockIdx.x;
    const int b    = be >> 4;          // / EE
    const int e    = be & (EE - 1);
    const float* g = g_logits + (size_t)be * NN;

    // load two consecutive tokens per thread (coalesced float2)
    const float2 v = *reinterpret_cast<const float2*>(g + 2 * tid);

    // block max
    float m = fmaxf(v.x, v.y);
#pragma unroll
    for (int s = 16; s > 0; s >>= 1) m = fmaxf(m, __shfl_xor_sync(0xffffffffu, m, s));
    if (lane == 0) red[wid] = m;
    __syncthreads();
    if (wid == 0) {
        float t = red[lane];
#pragma unroll
        for (int s = 16; s > 0; s >>= 1) t = fmaxf(t, __shfl_xor_sync(0xffffffffu, t, s));
        if (lane == 0) red[0] = t;
    }
    __syncthreads();
    m = red[0];
    __syncthreads();

    // exp + block sum
    const float u0 = expf(v.x - m);
    const float u1 = expf(v.y - m);
    float loc = u0 + u1;
#pragma unroll
    for (int s = 16; s > 0; s >>= 1) loc += __shfl_xor_sync(0xffffffffu, loc, s);
    if (lane == 0) red[wid] = loc;
    __syncthreads();
    if (wid == 0) {
        float t = red[lane];
#pragma unroll
        for (int s = 16; s > 0; s >>= 1) t += __shfl_xor_sync(0xffffffffu, t, s);
        if (lane == 0) red[0] = t;
    }
    __syncthreads();
    const float ssum = red[0];

    // affinity (with subnormal flush) + register sort keys
    float a0 = u0 / ssum;                       // IEEE div (no fast-math)
    float a1 = u1 / ssum;
    if (a0 < FLT_MIN_NORMAL) a0 = 0.0f;         // match reference FTZ zero-set
    if (a1 < FLT_MIN_NORMAL) a1 = 0.0f;
    aff[2 * tid]     = a0;
    aff[2 * tid + 1] = a1;
    u64 k0 = ((u64)__float_as_uint(a0) << 32) | (unsigned)(NN - 1 - 2 * tid);
    u64 k1 = ((u64)__float_as_uint(a1) << 32) | (unsigned)(NN - 1 - (2 * tid + 1));

    // bitonic sort (final order: descending)
    int pbuf = 0;
    const int i0 = 2 * tid;                     // index of k0 (k1 = i0+1)
    for (int kk = 2; kk <= NN; kk <<= 1) {
        const bool desc = ((i0 & kk) == 0);     // same for both owned elements (kk >= 2)
        int j = kk >> 1;
        // cross-warp stages: smem exchange, one barrier each
        for (; j >= 64; j >>= 1) {
            xbuf[pbuf][i0]     = k0;
            xbuf[pbuf][i0 + 1] = k1;
            __syncthreads();
            const u64 p0 = xbuf[pbuf][i0 ^ j];
            const u64 p1 = xbuf[pbuf][(i0 + 1) ^ j];
            const bool low = ((i0 & j) == 0);   // j >= 64 -> same for both elements
            const bool keepmax = (desc == low);
            k0 = keepmax ? (k0 > p0 ? k0 : p0) : (k0 < p0 ? k0 : p0);
            k1 = keepmax ? (k1 > p1 ? k1 : p1) : (k1 < p1 ? k1 : p1);
            pbuf ^= 1;                          // next write goes to other buffer: no 2nd barrier
        }
        // warp-local stages: partner thread = t ^ (j/2), same slot
        for (; j >= 2; j >>= 1) {
            const int lm = j >> 1;              // 1..16
            const u64 p0 = __shfl_xor_sync(0xffffffffu, k0, lm);
            const u64 p1 = __shfl_xor_sync(0xffffffffu, k1, lm);
            const bool low = ((tid & lm) == 0); // (i & j) == 0  <=>  (t & (j/2)) == 0
            const bool keepmax = (desc == low);
            k0 = keepmax ? (k0 > p0 ? k0 : p0) : (k0 < p0 ? k0 : p0);
            k1 = keepmax ? (k1 > p1 ? k1 : p1) : (k1 < p1 ? k1 : p1);
        }
        // j == 1: in-thread (k0 is the lower index -> gets max when descending)
        {
            const u64 mx = k0 > k1 ? k0 : k1;
            const u64 mn = k0 > k1 ? k1 : k0;
            k0 = desc ? mx : mn;
            k1 = desc ? mn : mx;
        }
    }

    // scatter: thread t holds rank slots c = 2t and 2t+1. Output already zeroed.
    // (aff[] visibility across threads is established by the sort's barriers.)
    if (tid < CC / 2) {
        const int tok0 = (NN - 1) - (int)(unsigned)(k0 & 0xffffffffu);
        const int tok1 = (NN - 1) - (int)(unsigned)(k1 & 0xffffffffu);
        const size_t a0i = (((size_t)(b * NN + tok0) * EE) + e) * CC + (2 * tid);
        const size_t a1i = (((size_t)(b * NN + tok1) * EE) + e) * CC + (2 * tid + 1);
        out[a0i]              = 1.0f;        // dispatch
        out[DISP_ELEMS + a0i] = aff[tok0];   // combine
        out[a1i]              = 1.0f;
        out[DISP_ELEMS + a1i] = aff[tok1];
    }
}

// ---------------------------------------------------------------------------
extern "C" void kernel_launch(void* const* d_in, const int* in_sizes, int n_in,
                              void* d_out, int out_size)
{
    const float* key   = (const float*)d_in[0];   // [B,N,D]
    const float* query = (const float*)d_in[1];   // [E,D]
    const float* temp  = (const float*)d_in[2];   // scalar log-temp

    (void)in_sizes; (void)n_in; (void)out_size;

    fused_logits_zfill_kernel<<<TOTAL_BLOCKS, 128>>>(key, query, temp, (float*)d_out);
    topk_scatter_kernel<<<BE, 1024>>>((float*)d_out);
}